// round 1
// baseline (speedup 1.0000x reference)
#include <cuda_runtime.h>

// LabelLoss: out[b] = sum_{n,c<7} (pred[b,n,c] - gt[b,n,c])^2
// pred, gt: [256, 16384, 8] fp32. Pure HBM-bound streaming reduction.

#define B_DIM     256
#define N_OBJ     16384
#define THREADS   256
#define SPLIT     8                     // blocks per batch row
#define OBJ_PER_BLK (N_OBJ / SPLIT)     // 2048 objects per block

__global__ void zero_out_kernel(float* __restrict__ out) {
    int i = threadIdx.x;
    if (i < B_DIM) out[i] = 0.0f;
}

__global__ __launch_bounds__(THREADS, 8)
void label_loss_kernel(const float* __restrict__ pred,
                       const float* __restrict__ gt,
                       float* __restrict__ out) {
    const int b = blockIdx.x;
    const int s = blockIdx.y;

    // Each object = 8 floats = 2 float4. Per batch row: 32768 float4.
    const float4* __restrict__ p =
        reinterpret_cast<const float4*>(pred) + (size_t)b * (N_OBJ * 2);
    const float4* __restrict__ g =
        reinterpret_cast<const float4*>(gt)   + (size_t)b * (N_OBJ * 2);

    float acc = 0.0f;

    // Objects handled by this block: [s*OBJ_PER_BLK, (s+1)*OBJ_PER_BLK)
    const int obj_base = s * OBJ_PER_BLK;

    #pragma unroll 4
    for (int i = threadIdx.x; i < OBJ_PER_BLK; i += THREADS) {
        const int j = (obj_base + i) * 2;   // float4 index of channels 0-3
        float4 p0 = p[j];
        float4 p1 = p[j + 1];
        float4 g0 = g[j];
        float4 g1 = g[j + 1];

        float d0 = p0.x - g0.x;
        float d1 = p0.y - g0.y;
        float d2 = p0.z - g0.z;
        float d3 = p0.w - g0.w;
        float d4 = p1.x - g1.x;
        float d5 = p1.y - g1.y;
        float d6 = p1.z - g1.z;
        // channel 7 (p1.w) excluded from the loss

        acc += d0*d0 + d1*d1 + d2*d2 + d3*d3 + d4*d4 + d5*d5 + d6*d6;
    }

    // Warp reduction
    #pragma unroll
    for (int off = 16; off > 0; off >>= 1)
        acc += __shfl_xor_sync(0xFFFFFFFFu, acc, off);

    // Cross-warp reduction via shared memory
    __shared__ float warp_sums[THREADS / 32];
    const int lane = threadIdx.x & 31;
    const int wid  = threadIdx.x >> 5;
    if (lane == 0) warp_sums[wid] = acc;
    __syncthreads();

    if (wid == 0) {
        float v = (lane < THREADS / 32) ? warp_sums[lane] : 0.0f;
        #pragma unroll
        for (int off = 4; off > 0; off >>= 1)
            v += __shfl_xor_sync(0xFFFFFFFFu, v, off);
        if (lane == 0)
            atomicAdd(out + b, v);
    }
}

extern "C" void kernel_launch(void* const* d_in, const int* in_sizes, int n_in,
                              void* d_out, int out_size) {
    const float* pred = (const float*)d_in[0];
    const float* gt   = (const float*)d_in[1];
    float* out        = (float*)d_out;

    zero_out_kernel<<<1, B_DIM>>>(out);

    dim3 grid(B_DIM, SPLIT);
    label_loss_kernel<<<grid, THREADS>>>(pred, gt, out);
}

// round 2
// speedup vs baseline: 1.0941x; 1.0941x over previous
#include <cuda_runtime.h>

// LabelLoss: out[b] = sum_{n,c<7} (pred[b,n,c] - gt[b,n,c])^2
// pred, gt: [256, 16384, 8] fp32. Pure HBM-bound streaming reduction.
//
// R2: fully-coalesced float4 stream (consecutive lanes -> consecutive float4),
// channel-7 masked by per-thread constant (parity of float4 index is fixed
// because the stride is even). Grid sized to a single wave (1024 blocks).

#define B_DIM       256
#define N_OBJ       16384
#define THREADS     256
#define SPLIT       4                         // blocks per batch row -> grid 1024
#define F4_PER_ROW  (N_OBJ * 2)               // 32768 float4 per batch row
#define F4_PER_BLK  (F4_PER_ROW / SPLIT)      // 8192 float4 per block
#define UNROLL      4

__global__ void zero_out_kernel(float* __restrict__ out) {
    int i = threadIdx.x;
    if (i < B_DIM) out[i] = 0.0f;
}

__global__ __launch_bounds__(THREADS, 8)
void label_loss_kernel(const float* __restrict__ pred,
                       const float* __restrict__ gt,
                       float* __restrict__ out) {
    const int b = blockIdx.x;
    const int s = blockIdx.y;

    const float4* __restrict__ p =
        reinterpret_cast<const float4*>(pred) + (size_t)b * F4_PER_ROW + s * F4_PER_BLK;
    const float4* __restrict__ g =
        reinterpret_cast<const float4*>(gt)   + (size_t)b * F4_PER_ROW + s * F4_PER_BLK;

    // float4 index parity for this thread is constant (stride THREADS is even,
    // block base F4_PER_BLK*s is even): odd float4 -> its .w is channel 7 (excluded).
    const float wsel = (threadIdx.x & 1) ? 0.0f : 1.0f;

    float acc = 0.0f;

    // 8192 float4 / (256 threads * 4 unroll) = 8 outer iterations
    #pragma unroll 1
    for (int base = 0; base < F4_PER_BLK; base += THREADS * UNROLL) {
        float4 pv[UNROLL], gv[UNROLL];
        #pragma unroll
        for (int u = 0; u < UNROLL; u++) {
            const int idx = base + u * THREADS + threadIdx.x;
            pv[u] = p[idx];
            gv[u] = g[idx];
        }
        #pragma unroll
        for (int u = 0; u < UNROLL; u++) {
            float d0 = pv[u].x - gv[u].x;
            float d1 = pv[u].y - gv[u].y;
            float d2 = pv[u].z - gv[u].z;
            float d3 = (pv[u].w - gv[u].w) * wsel;   // channel 7 masked on odd lanes
            acc += d0*d0 + d1*d1 + d2*d2 + d3*d3;
        }
    }

    // Warp reduction
    #pragma unroll
    for (int off = 16; off > 0; off >>= 1)
        acc += __shfl_xor_sync(0xFFFFFFFFu, acc, off);

    // Cross-warp reduction via shared memory
    __shared__ float warp_sums[THREADS / 32];
    const int lane = threadIdx.x & 31;
    const int wid  = threadIdx.x >> 5;
    if (lane == 0) warp_sums[wid] = acc;
    __syncthreads();

    if (wid == 0) {
        float v = (lane < THREADS / 32) ? warp_sums[lane] : 0.0f;
        #pragma unroll
        for (int off = 4; off > 0; off >>= 1)
            v += __shfl_xor_sync(0xFFFFFFFFu, v, off);
        if (lane == 0)
            atomicAdd(out + b, v);
    }
}

extern "C" void kernel_launch(void* const* d_in, const int* in_sizes, int n_in,
                              void* d_out, int out_size) {
    const float* pred = (const float*)d_in[0];
    const float* gt   = (const float*)d_in[1];
    float* out        = (float*)d_out;

    zero_out_kernel<<<1, B_DIM>>>(out);

    dim3 grid(B_DIM, SPLIT);
    label_loss_kernel<<<grid, THREADS>>>(pred, gt, out);
}